// round 16
// baseline (speedup 1.0000x reference)
#include <cuda_runtime.h>
#include <cstdint>

#define VOCAB 200000
#define EMBED 128
#define N_POS 10
#define N_NEG 64
#define N_SCORES (N_POS + N_NEG)            // 74
#define N_ROWS (1 + N_SCORES)               // 75

#define THREADS 256
#define QPT 25                              // float4 quads per thread
#define QPB (THREADS * QPT)                 // 6400 quads per block
#define N_QUADS (VOCAB / 4)                 // 50000
#define BLOCKS_X ((N_QUADS + QPB - 1) / QPB)    // 8
#define TOTAL_BLOCKS (BLOCKS_X * N_ROWS)        // 600 (single wave)
#define S_STAGES 10                         // cp.async ring depth (40 KB smem)
#define STEADY (QPT - S_STAGES)             // 15

// Scratch. slot 0 = center, 1..10 = pos, 11..74 = neg.
__device__ int g_idx[N_ROWS];
// Ticket counter; last block resets it -> deterministic across graph replays.
__device__ unsigned int g_done;

__device__ __forceinline__ float log_sigmoid(float x) {
    return fminf(x, 0.0f) - log1pf(__expf(-fabsf(x)));   // stable
}

__device__ __forceinline__ void l2_prefetch(const void* p) {
    asm volatile("prefetch.global.L2 [%0];" :: "l"(p));
}

// 16-byte async copy, L2-only (.cg): no dst register, no scoreboard slot.
__device__ __forceinline__ void cp_async16(unsigned int dst_smem, const void* src) {
    asm volatile("cp.async.cg.shared.global [%0], [%1], 16;"
                 :: "r"(dst_smem), "l"(src));
}
__device__ __forceinline__ void cp_commit() {
    asm volatile("cp.async.commit_group;");
}
template <int N>
__device__ __forceinline__ void cp_wait() {
    asm volatile("cp.async.wait_group %0;" :: "n"(N));
}

__global__ void __launch_bounds__(THREADS)
skipgram_kernel(const float* __restrict__ center,
                const float* __restrict__ pos,
                const float* __restrict__ neg,
                const float* __restrict__ in_emb,    // [EMBED, VOCAB]
                const float* __restrict__ out_emb,   // [VOCAB, EMBED]
                float* __restrict__ out)
{
    __shared__ float4 ring[S_STAGES][THREADS];       // 40960 B
    __shared__ int   sidx[N_ROWS];
    __shared__ float ctr[EMBED];
    __shared__ float wsum[8];
    __shared__ bool  am_last;

    const int tid = threadIdx.x;
    const int row = blockIdx.y;

    const float* base;
    if (row == 0)            base = center;
    else if (row <= N_POS)   base = pos + (size_t)(row - 1) * VOCAB;
    else                     base = neg + (size_t)(row - 1 - N_POS) * VOCAB;

    const int qbase = blockIdx.x * QPB;              // first quad of this block
    const int q0    = qbase + tid;                   // chunk-0 quad for this thread
    const float4* tb = reinterpret_cast<const float4*>(base) + q0;

    const unsigned int my_slot0 =
        (unsigned int)__cvta_generic_to_shared(&ring[0][tid]);   // +4096 per stage

    // ---- Scan: weighted one-hot locate via cp.async ring, S_STAGES in flight.
    // acc = sum v * (c*1024 + k + 1); exact (entries exactly 1.0/0.0, weights < 2^24).
    float acc0 = 0.0f, acc1 = 0.0f;

    #pragma unroll
    for (int c = 0; c < S_STAGES; c++) {             // prologue: fill ring
        if (q0 + c * THREADS < N_QUADS)
            cp_async16(my_slot0 + c * (THREADS * 16), tb + c * THREADS);
        cp_commit();                                 // empty group ok on tail
    }

    #pragma unroll
    for (int c = 0; c < STEADY; c++) {               // steady: consume c, refill c+S
        cp_wait<S_STAGES - 1>();                     // chunk c's group complete
        const int st = c % S_STAGES;
        const float4 cur = ring[st][tid];            // my own slot: no block sync
        if (q0 + (c + S_STAGES) * THREADS < N_QUADS)
            cp_async16(my_slot0 + st * (THREADS * 16), tb + (c + S_STAGES) * THREADS);
        cp_commit();
        if (q0 + c * THREADS < N_QUADS) {
            const float r = (float)(c * 1024 + 1);
            acc0 = fmaf(cur.x, r,        acc0);
            acc1 = fmaf(cur.y, r + 1.0f, acc1);
            acc0 = fmaf(cur.z, r + 2.0f, acc0);
            acc1 = fmaf(cur.w, r + 3.0f, acc1);
        }
    }

    cp_wait<0>();                                    // drain remaining S stages
    #pragma unroll
    for (int c = STEADY; c < QPT; c++) {
        if (q0 + c * THREADS < N_QUADS) {
            const float4 cur = ring[c % S_STAGES][tid];
            const float r = (float)(c * 1024 + 1);
            acc0 = fmaf(cur.x, r,        acc0);
            acc1 = fmaf(cur.y, r + 1.0f, acc1);
            acc0 = fmaf(cur.z, r + 2.0f, acc0);
            acc1 = fmaf(cur.w, r + 3.0f, acc1);
        }
    }

    const float acc = acc0 + acc1;
    if (acc != 0.0f) {                               // exactly one finder per row
        const int idx = q0 * 4 + (int)acc - 1;
        g_idx[row] = idx;
        // warm L2 for the epilogue gather of this row
        if (row > N_POS) {                           // negative: contiguous 512B row
            const char* p = (const char*)(out_emb + (size_t)idx * EMBED);
            #pragma unroll
            for (int j = 0; j < 4; j++) l2_prefetch(p + j * 128);
        } else {                                     // center/positive: strided column
            for (int k = 0; k < EMBED; k++)
                l2_prefetch(in_emb + (size_t)k * VOCAB + idx);
        }
    }

    // ---- Last-block handoff ----
    __syncthreads();
    if (tid == 0) {
        __threadfence();
        am_last = (atomicAdd(&g_done, 1u) == TOTAL_BLOCKS - 1);
    }
    __syncthreads();
    if (!am_last) return;
    __threadfence();

    // ---- Epilogue: 74 dots + log-sigmoid (L2 warm from prefetches) ----
    if (tid < N_ROWS) sidx[tid] = g_idx[tid];
    __syncthreads();
    const int c = sidx[0];
    if (tid < EMBED) ctr[tid] = in_emb[(size_t)tid * VOCAB + c];
    __syncthreads();

    const int warp = tid >> 5;                       // 0..7
    const int lane = tid & 31;

    float dot[10];
    #pragma unroll
    for (int j = 0; j < 10; j++) dot[j] = 0.0f;

    #pragma unroll
    for (int j = 0; j < 10; j++) {
        const int s = warp + 8 * j;
        if (s < N_SCORES) {
            const int idx = sidx[s + 1];
            if (s < N_POS) {
                #pragma unroll
                for (int k = lane; k < EMBED; k += 32)
                    dot[j] = fmaf(ctr[k], in_emb[(size_t)k * VOCAB + idx], dot[j]);
            } else {
                #pragma unroll
                for (int k = lane; k < EMBED; k += 32)
                    dot[j] = fmaf(ctr[k], out_emb[(size_t)idx * EMBED + k], dot[j]);
            }
        }
    }

    float local = 0.0f;
    #pragma unroll
    for (int j = 0; j < 10; j++) {
        const int s = warp + 8 * j;
        #pragma unroll
        for (int o = 16; o; o >>= 1)
            dot[j] += __shfl_xor_sync(0xFFFFFFFFu, dot[j], o);
        if (lane == 0 && s < N_SCORES)
            local += log_sigmoid((s < N_POS) ? dot[j] : -dot[j]);
    }

    if (lane == 0) wsum[warp] = local;
    __syncthreads();

    if (tid == 0) {
        float a = 0.0f;
        #pragma unroll
        for (int w = 0; w < 8; w++) a += wsum[w];
        out[0] = -a;
        g_done = 0;                                  // reset for next replay
    }
}

// ---------------------------------------------------------------------------
// Inputs (metadata order):
//   d_in[0] center_word        [200000]        f32
//   d_in[1] positive_words     [10, 200000]    f32
//   d_in[2] negative_words     [64, 200000]    f32
//   d_in[3] input_embeddings   [128, 200000]   f32
//   d_in[4] output_embeddings  [200000, 128]   f32
// d_out: 1 x f32 scalar loss
// ---------------------------------------------------------------------------
extern "C" void kernel_launch(void* const* d_in, const int* in_sizes, int n_in,
                              void* d_out, int out_size)
{
    const float* center = (const float*)d_in[0];
    const float* pos    = (const float*)d_in[1];
    const float* neg    = (const float*)d_in[2];
    const float* in_emb = (const float*)d_in[3];
    const float* ot_emb = (const float*)d_in[4];
    float* out          = (float*)d_out;

    dim3 grid(BLOCKS_X, N_ROWS);
    skipgram_kernel<<<grid, THREADS>>>(center, pos, neg, in_emb, ot_emb, out);
}